// round 4
// baseline (speedup 1.0000x reference)
#include <cuda_runtime.h>

typedef unsigned long long u64;

#define TT 32
#define BB 2048
#define DD 64
#define WWID 256
#define MROWS 16
#define NCTA (BB / MROWS)   // 128
#define NTHR 256

// Transposed weights, [k][n] layout so weight loads are lane-coalesced.
__device__ __align__(16) float g_W0t[DD * WWID];    // 64 x 256
__device__ __align__(16) float g_W1t[WWID * WWID];  // 256 x 256
__device__ __align__(16) float g_W2t[WWID * DD];    // 256 x 64

__global__ void prep_kernel(const float* __restrict__ W0,
                            const float* __restrict__ W1,
                            const float* __restrict__ W2) {
    int idx = blockIdx.x * blockDim.x + threadIdx.x;
    if (idx < DD * WWID) {              // W0t[k][n] = W0[n][k]
        int k = idx >> 8, n = idx & 255;
        g_W0t[idx] = W0[n * DD + k];
    }
    if (idx < WWID * WWID) {            // W1t[k][n] = W1[n][k]
        int k = idx >> 8, n = idx & 255;
        g_W1t[idx] = W1[n * WWID + k];
    }
    if (idx < WWID * DD) {              // W2t[k][d] = W2[d][k]
        int k = idx >> 6, d = idx & 63;
        g_W2t[idx] = W2[d * WWID + k];
    }
}

// ---- packed f32x2 helpers (ptxas never auto-fuses; must be PTX) ----
__device__ __forceinline__ u64 pk2(float x) {
    u64 r; asm("mov.b64 %0, {%1, %1};" : "=l"(r) : "f"(x)); return r;
}
__device__ __forceinline__ u64 fma2(u64 a, u64 b, u64 c) {
    u64 d; asm("fma.rn.f32x2 %0, %1, %2, %3;" : "=l"(d) : "l"(a), "l"(b), "l"(c));
    return d;
}
__device__ __forceinline__ void upk2(u64 v, float& lo, float& hi) {
    asm("mov.b64 {%0, %1}, %2;" : "=f"(lo), "=f"(hi) : "l"(v));
}

__device__ __forceinline__ float tanh_fast(float x) {
    // exact identity tanh(x) = 1 - 2/(e^{2x}+1); ~1e-6 abs err with fast exp/div
    float e = __expf(2.0f * x);
    return 1.0f - __fdividef(2.0f, e + 1.0f);
}

__device__ __forceinline__ float4 f4fma(float4 a, float s, float4 b) {
    a.x = fmaf(s, b.x, a.x); a.y = fmaf(s, b.y, a.y);
    a.z = fmaf(s, b.z, a.z); a.w = fmaf(s, b.w, a.w);
    return a;
}

// Hidden layer: out[16][256] = tanh(x[16][K] @ Wt(K x 256) + bias), 256 threads.
// Thread tile: 4 rows x 4 cols, math in packed f32x2 (FFMA2).
// A-loads: warp-broadcast LDS.128. W-loads: coalesced LDG.128 (as ulonglong2).
__device__ __forceinline__ void dense_h(const float* __restrict__ x, int K,
                                        const float* __restrict__ Wt,
                                        const float* __restrict__ bias,
                                        float* __restrict__ o, int tid) {
    const int r0 = (tid >> 6) << 2;   // 0,4,8,12
    const int c0 = (tid & 63) << 2;   // 0..252
    u64 acc[4][2];
    {
        ulonglong2 bv = *reinterpret_cast<const ulonglong2*>(bias + c0);
        #pragma unroll
        for (int r = 0; r < 4; ++r) { acc[r][0] = bv.x; acc[r][1] = bv.y; }
    }
    const float* xp0 = x + r0 * K;
    const float* xp1 = xp0 + K;
    const float* xp2 = xp1 + K;
    const float* xp3 = xp2 + K;
    const float* wp = Wt + c0;
    #pragma unroll 2
    for (int k = 0; k < K; k += 4) {
        float4 a0 = *reinterpret_cast<const float4*>(xp0 + k);
        float4 a1 = *reinterpret_cast<const float4*>(xp1 + k);
        float4 a2 = *reinterpret_cast<const float4*>(xp2 + k);
        float4 a3 = *reinterpret_cast<const float4*>(xp3 + k);
        ulonglong2 w0 = *reinterpret_cast<const ulonglong2*>(wp);
        ulonglong2 w1 = *reinterpret_cast<const ulonglong2*>(wp + 256);
        ulonglong2 w2 = *reinterpret_cast<const ulonglong2*>(wp + 512);
        ulonglong2 w3 = *reinterpret_cast<const ulonglong2*>(wp + 768);
        wp += 1024;
        u64 s;
        // kk = 0
        s = pk2(a0.x); acc[0][0] = fma2(s, w0.x, acc[0][0]); acc[0][1] = fma2(s, w0.y, acc[0][1]);
        s = pk2(a1.x); acc[1][0] = fma2(s, w0.x, acc[1][0]); acc[1][1] = fma2(s, w0.y, acc[1][1]);
        s = pk2(a2.x); acc[2][0] = fma2(s, w0.x, acc[2][0]); acc[2][1] = fma2(s, w0.y, acc[2][1]);
        s = pk2(a3.x); acc[3][0] = fma2(s, w0.x, acc[3][0]); acc[3][1] = fma2(s, w0.y, acc[3][1]);
        // kk = 1
        s = pk2(a0.y); acc[0][0] = fma2(s, w1.x, acc[0][0]); acc[0][1] = fma2(s, w1.y, acc[0][1]);
        s = pk2(a1.y); acc[1][0] = fma2(s, w1.x, acc[1][0]); acc[1][1] = fma2(s, w1.y, acc[1][1]);
        s = pk2(a2.y); acc[2][0] = fma2(s, w1.x, acc[2][0]); acc[2][1] = fma2(s, w1.y, acc[2][1]);
        s = pk2(a3.y); acc[3][0] = fma2(s, w1.x, acc[3][0]); acc[3][1] = fma2(s, w1.y, acc[3][1]);
        // kk = 2
        s = pk2(a0.z); acc[0][0] = fma2(s, w2.x, acc[0][0]); acc[0][1] = fma2(s, w2.y, acc[0][1]);
        s = pk2(a1.z); acc[1][0] = fma2(s, w2.x, acc[1][0]); acc[1][1] = fma2(s, w2.y, acc[1][1]);
        s = pk2(a2.z); acc[2][0] = fma2(s, w2.x, acc[2][0]); acc[2][1] = fma2(s, w2.y, acc[2][1]);
        s = pk2(a3.z); acc[3][0] = fma2(s, w2.x, acc[3][0]); acc[3][1] = fma2(s, w2.y, acc[3][1]);
        // kk = 3
        s = pk2(a0.w); acc[0][0] = fma2(s, w3.x, acc[0][0]); acc[0][1] = fma2(s, w3.y, acc[0][1]);
        s = pk2(a1.w); acc[1][0] = fma2(s, w3.x, acc[1][0]); acc[1][1] = fma2(s, w3.y, acc[1][1]);
        s = pk2(a2.w); acc[2][0] = fma2(s, w3.x, acc[2][0]); acc[2][1] = fma2(s, w3.y, acc[2][1]);
        s = pk2(a3.w); acc[3][0] = fma2(s, w3.x, acc[3][0]); acc[3][1] = fma2(s, w3.y, acc[3][1]);
    }
    #pragma unroll
    for (int r = 0; r < 4; ++r) {
        float v0, v1, v2, v3;
        upk2(acc[r][0], v0, v1); upk2(acc[r][1], v2, v3);
        float4 rr;
        rr.x = tanh_fast(v0); rr.y = tanh_fast(v1);
        rr.z = tanh_fast(v2); rr.w = tanh_fast(v3);
        *reinterpret_cast<float4*>(o + (r0 + r) * WWID + c0) = rr;
    }
}

// Output layer: k[16][64] = (x[16][256] @ W2t(256 x 64) + b2) * efac
// 256 threads: 1 row x 4 cols (2 f32x2 accumulators per thread).
__device__ __forceinline__ void dense_o(const float* __restrict__ x,
                                        const float* __restrict__ Wt,
                                        const float* __restrict__ bias,
                                        float* __restrict__ o, float efac, int tid) {
    const int row = tid >> 4;         // 0..15
    const int c0 = (tid & 15) << 2;   // 0..60
    u64 acca, accb;
    {
        ulonglong2 bv = *reinterpret_cast<const ulonglong2*>(bias + c0);
        acca = bv.x; accb = bv.y;
    }
    const float* xp = x + row * WWID;
    const float* wp = Wt + c0;
    #pragma unroll 2
    for (int k = 0; k < WWID; k += 4) {
        float4 a = *reinterpret_cast<const float4*>(xp + k);
        ulonglong2 w0 = *reinterpret_cast<const ulonglong2*>(wp);
        ulonglong2 w1 = *reinterpret_cast<const ulonglong2*>(wp + 64);
        ulonglong2 w2 = *reinterpret_cast<const ulonglong2*>(wp + 128);
        ulonglong2 w3 = *reinterpret_cast<const ulonglong2*>(wp + 192);
        wp += 256;
        u64 s;
        s = pk2(a.x); acca = fma2(s, w0.x, acca); accb = fma2(s, w0.y, accb);
        s = pk2(a.y); acca = fma2(s, w1.x, acca); accb = fma2(s, w1.y, accb);
        s = pk2(a.z); acca = fma2(s, w2.x, acca); accb = fma2(s, w2.y, accb);
        s = pk2(a.w); acca = fma2(s, w3.x, acca); accb = fma2(s, w3.y, accb);
    }
    float v0, v1, v2, v3;
    upk2(acca, v0, v1); upk2(accb, v2, v3);
    float4 r;
    r.x = v0 * efac; r.y = v1 * efac; r.z = v2 * efac; r.w = v3 * efac;
    *reinterpret_cast<float4*>(o + row * DD + c0) = r;
}

// smem layout (floats)
#define OFF_SY   0
#define OFF_SYT  (OFF_SY + MROWS * DD)        // 1024
#define OFF_SH0  (OFF_SYT + MROWS * DD)       // 2048
#define OFF_SH1  (OFF_SH0 + MROWS * WWID)     // 6144
#define OFF_SK   (OFF_SH1 + MROWS * WWID)     // 10240
#define OFF_SB0  (OFF_SK + 6 * MROWS * DD)    // 16384
#define OFF_SB1  (OFF_SB0 + WWID)             // 16640
#define OFF_SB2  (OFF_SB1 + WWID)             // 16896
#define OFF_STS  (OFF_SB2 + DD)               // 16960
#define SMEM_FLOATS (OFF_STS + TT)            // 16992

__global__ void __launch_bounds__(NTHR)
ode_kernel(const float* __restrict__ ts, const float* __restrict__ y0,
           const float* __restrict__ b0, const float* __restrict__ b1,
           const float* __restrict__ b2, float* __restrict__ out) {
    extern __shared__ float sm[];
    float* sy  = sm + OFF_SY;
    float* syt = sm + OFF_SYT;
    float* sh0 = sm + OFF_SH0;
    float* sh1 = sm + OFF_SH1;
    float* sk  = sm + OFF_SK;
    float* sb0 = sm + OFF_SB0;
    float* sb1 = sm + OFF_SB1;
    float* sb2 = sm + OFF_SB2;
    float* sts = sm + OFF_STS;

    const int tid = threadIdx.x;
    const int rb = blockIdx.x * MROWS;

    // Init: load y0 slice, biases, ts; write t=0 output slice.
    {
        float4 v = reinterpret_cast<const float4*>(y0)[rb * (DD / 4) + tid];
        reinterpret_cast<float4*>(sy)[tid] = v;
        reinterpret_cast<float4*>(out)[rb * (DD / 4) + tid] = v;
        sb0[tid] = b0[tid];
        sb1[tid] = b1[tid];
        if (tid < DD) sb2[tid] = b2[tid];
        if (tid < TT) sts[tid] = ts[tid];
    }
    __syncthreads();

    float4* sy4  = reinterpret_cast<float4*>(sy);
    float4* syt4 = reinterpret_cast<float4*>(syt);
    float4* k14  = reinterpret_cast<float4*>(sk + 0 * MROWS * DD);
    float4* k24  = reinterpret_cast<float4*>(sk + 1 * MROWS * DD);
    float4* k34  = reinterpret_cast<float4*>(sk + 2 * MROWS * DD);
    float4* k44  = reinterpret_cast<float4*>(sk + 3 * MROWS * DD);
    float4* k54  = reinterpret_cast<float4*>(sk + 4 * MROWS * DD);
    float4* k64  = reinterpret_cast<float4*>(sk + 5 * MROWS * DD);

    for (int iv = 0; iv < TT - 1; ++iv) {
        const float t0 = sts[iv];
        const float dt = sts[iv + 1] - t0;
        const float h = 0.5f * dt;

        for (int sub = 0; sub < 2; ++sub) {
            const float tc = t0 + (float)sub * h;

            // ---- stage 1: k1 = vf(tc, y) ----
            dense_h(sy, DD, g_W0t, sb0, sh0, tid);  __syncthreads();
            dense_h(sh0, WWID, g_W1t, sb1, sh1, tid); __syncthreads();
            dense_o(sh1, g_W2t, sb2, sk + 0 * MROWS * DD, __expf(tc), tid); __syncthreads();

            // ---- stage 2 ----
            syt4[tid] = f4fma(sy4[tid], h * 0.2f, k14[tid]);
            __syncthreads();
            dense_h(syt, DD, g_W0t, sb0, sh0, tid);  __syncthreads();
            dense_h(sh0, WWID, g_W1t, sb1, sh1, tid); __syncthreads();
            dense_o(sh1, g_W2t, sb2, sk + 1 * MROWS * DD, __expf(tc + 0.2f * h), tid); __syncthreads();

            // ---- stage 3 ----
            {
                float4 v = sy4[tid];
                v = f4fma(v, h * (3.0f / 40.0f), k14[tid]);
                v = f4fma(v, h * (9.0f / 40.0f), k24[tid]);
                syt4[tid] = v;
            }
            __syncthreads();
            dense_h(syt, DD, g_W0t, sb0, sh0, tid);  __syncthreads();
            dense_h(sh0, WWID, g_W1t, sb1, sh1, tid); __syncthreads();
            dense_o(sh1, g_W2t, sb2, sk + 2 * MROWS * DD, __expf(tc + 0.3f * h), tid); __syncthreads();

            // ---- stage 4 ----
            {
                float4 v = sy4[tid];
                v = f4fma(v, h * (44.0f / 45.0f),  k14[tid]);
                v = f4fma(v, h * (-56.0f / 15.0f), k24[tid]);
                v = f4fma(v, h * (32.0f / 9.0f),   k34[tid]);
                syt4[tid] = v;
            }
            __syncthreads();
            dense_h(syt, DD, g_W0t, sb0, sh0, tid);  __syncthreads();
            dense_h(sh0, WWID, g_W1t, sb1, sh1, tid); __syncthreads();
            dense_o(sh1, g_W2t, sb2, sk + 3 * MROWS * DD, __expf(tc + 0.8f * h), tid); __syncthreads();

            // ---- stage 5 ----
            {
                float4 v = sy4[tid];
                v = f4fma(v, h * (19372.0f / 6561.0f),  k14[tid]);
                v = f4fma(v, h * (-25360.0f / 2187.0f), k24[tid]);
                v = f4fma(v, h * (64448.0f / 6561.0f),  k34[tid]);
                v = f4fma(v, h * (-212.0f / 729.0f),    k44[tid]);
                syt4[tid] = v;
            }
            __syncthreads();
            dense_h(syt, DD, g_W0t, sb0, sh0, tid);  __syncthreads();
            dense_h(sh0, WWID, g_W1t, sb1, sh1, tid); __syncthreads();
            dense_o(sh1, g_W2t, sb2, sk + 4 * MROWS * DD, __expf(tc + (8.0f / 9.0f) * h), tid); __syncthreads();

            // ---- stage 6 ----
            {
                float4 v = sy4[tid];
                v = f4fma(v, h * (9017.0f / 3168.0f),   k14[tid]);
                v = f4fma(v, h * (-355.0f / 33.0f),     k24[tid]);
                v = f4fma(v, h * (46732.0f / 5247.0f),  k34[tid]);
                v = f4fma(v, h * (49.0f / 176.0f),      k44[tid]);
                v = f4fma(v, h * (-5103.0f / 18656.0f), k54[tid]);
                syt4[tid] = v;
            }
            __syncthreads();
            dense_h(syt, DD, g_W0t, sb0, sh0, tid);  __syncthreads();
            dense_h(sh0, WWID, g_W1t, sb1, sh1, tid); __syncthreads();
            dense_o(sh1, g_W2t, sb2, sk + 5 * MROWS * DD, __expf(tc + h), tid); __syncthreads();

            // ---- final combine ----
            {
                float4 v = sy4[tid];
                v = f4fma(v, h * (35.0f / 384.0f),     k14[tid]);
                v = f4fma(v, h * (500.0f / 1113.0f),   k34[tid]);
                v = f4fma(v, h * (125.0f / 192.0f),    k44[tid]);
                v = f4fma(v, h * (-2187.0f / 6784.0f), k54[tid]);
                v = f4fma(v, h * (11.0f / 84.0f),      k64[tid]);
                sy4[tid] = v;
            }
            __syncthreads();
        }

        // write output slice (iv+1)
        {
            float4 v = sy4[tid];
            reinterpret_cast<float4*>(out)[((iv + 1) * BB + rb) * (DD / 4) + tid] = v;
        }
    }
}

extern "C" void kernel_launch(void* const* d_in, const int* in_sizes, int n_in,
                              void* d_out, int out_size) {
    const float* ts = (const float*)d_in[0];
    const float* y0 = (const float*)d_in[1];
    const float* W0 = (const float*)d_in[2];
    const float* b0 = (const float*)d_in[3];
    const float* W1 = (const float*)d_in[4];
    const float* b1 = (const float*)d_in[5];
    const float* W2 = (const float*)d_in[6];
    const float* b2 = (const float*)d_in[7];
    float* out = (float*)d_out;

    prep_kernel<<<256, 256>>>(W0, W1, W2);

    size_t smem_bytes = SMEM_FLOATS * sizeof(float);
    cudaFuncSetAttribute(ode_kernel, cudaFuncAttributeMaxDynamicSharedMemorySize,
                         (int)smem_bytes);
    ode_kernel<<<NCTA, NTHR, smem_bytes>>>(ts, y0, b0, b1, b2, out);
}

// round 6
// speedup vs baseline: 1.8169x; 1.8169x over previous
#include <cuda_runtime.h>

#define TT 32
#define BB 2048
#define DD 64
#define WWID 256
#define MROWS 16
#define NCTA (BB / MROWS)   // 128
#define NTHR 512

// Transposed weights, [k][n] layout so weight loads are lane-coalesced.
__device__ __align__(16) float g_W0t[DD * WWID];    // 64 x 256
__device__ __align__(16) float g_W1t[WWID * WWID];  // 256 x 256
__device__ __align__(16) float g_W2t[WWID * DD];    // 256 x 64

__global__ void prep_kernel(const float* __restrict__ W0,
                            const float* __restrict__ W1,
                            const float* __restrict__ W2) {
    int idx = blockIdx.x * blockDim.x + threadIdx.x;
    if (idx < DD * WWID) {              // W0t[k][n] = W0[n][k]
        int k = idx >> 8, n = idx & 255;
        g_W0t[idx] = W0[n * DD + k];
    }
    if (idx < WWID * WWID) {            // W1t[k][n] = W1[n][k]
        int k = idx >> 8, n = idx & 255;
        g_W1t[idx] = W1[n * WWID + k];
    }
    if (idx < WWID * DD) {              // W2t[k][d] = W2[d][k]
        int k = idx >> 6, d = idx & 63;
        g_W2t[idx] = W2[d * WWID + k];
    }
}

__device__ __forceinline__ float tanh_fast(float x) {
    // exact identity tanh(x) = 1 - 2/(e^{2x}+1); ~1e-6 abs err with fast exp/div
    float e = __expf(2.0f * x);
    return 1.0f - __fdividef(2.0f, e + 1.0f);
}

__device__ __forceinline__ void ld4(float* d, const float* p) {
    float4 t = *reinterpret_cast<const float4*>(p);
    d[0] = t.x; d[1] = t.y; d[2] = t.z; d[3] = t.w;
}

__device__ __forceinline__ float2 f2fma(float2 a, float s, float2 b) {
    a.x = fmaf(s, b.x, a.x); a.y = fmaf(s, b.y, a.y);
    return a;
}

// Hidden layer, split-K over 2 k-groups of 256 threads each.
// out[16][256] = tanh(x[16][K] @ Wt(K x 256) + bias)
// Each group: 4 rows x 4 cols scalar-FFMA tile over its K/2 slice.
// Group 1 writes partials to sp; group 0 adds, applies tanh, stores.
__device__ __forceinline__ void dense_h(const float* __restrict__ x, int K,
                                        const float* __restrict__ Wt,
                                        const float* __restrict__ bias,
                                        float* __restrict__ o,
                                        float* __restrict__ sp, int tid) {
    const int kg = tid >> 8;          // 0 or 1
    const int t2 = tid & 255;
    const int r0 = (t2 >> 6) << 2;    // 0,4,8,12
    const int c0 = (t2 & 63) << 2;    // 0..252
    const int Kh = K >> 1;
    float acc[4][4];
    if (kg == 0) {
        float4 bv = *reinterpret_cast<const float4*>(bias + c0);
        #pragma unroll
        for (int r = 0; r < 4; ++r) {
            acc[r][0] = bv.x; acc[r][1] = bv.y; acc[r][2] = bv.z; acc[r][3] = bv.w;
        }
    } else {
        #pragma unroll
        for (int r = 0; r < 4; ++r)
            #pragma unroll
            for (int c = 0; c < 4; ++c) acc[r][c] = 0.0f;
    }
    const float* xp0 = x + r0 * K + kg * Kh;
    const float* xp1 = xp0 + K;
    const float* xp2 = xp1 + K;
    const float* xp3 = xp2 + K;
    const float* wp = Wt + kg * Kh * WWID + c0;
    #pragma unroll 2
    for (int k = 0; k < Kh; k += 4) {
        float a[4][4];   // [r][kk]
        float w[4][4];   // [kk][c]
        ld4(a[0], xp0 + k); ld4(a[1], xp1 + k);
        ld4(a[2], xp2 + k); ld4(a[3], xp3 + k);
        ld4(w[0], wp);        ld4(w[1], wp + 256);
        ld4(w[2], wp + 512);  ld4(w[3], wp + 768);
        wp += 1024;
        #pragma unroll
        for (int r = 0; r < 4; ++r)
            #pragma unroll
            for (int kk = 0; kk < 4; ++kk)
                #pragma unroll
                for (int c = 0; c < 4; ++c)
                    acc[r][c] = fmaf(a[r][kk], w[kk][c], acc[r][c]);
    }
    if (kg == 1) {
        #pragma unroll
        for (int r = 0; r < 4; ++r) {
            float4 v; v.x = acc[r][0]; v.y = acc[r][1]; v.z = acc[r][2]; v.w = acc[r][3];
            *reinterpret_cast<float4*>(sp + (r0 + r) * WWID + c0) = v;
        }
    }
    __syncthreads();
    if (kg == 0) {
        #pragma unroll
        for (int r = 0; r < 4; ++r) {
            float4 p = *reinterpret_cast<const float4*>(sp + (r0 + r) * WWID + c0);
            float4 v;
            v.x = tanh_fast(acc[r][0] + p.x);
            v.y = tanh_fast(acc[r][1] + p.y);
            v.z = tanh_fast(acc[r][2] + p.z);
            v.w = tanh_fast(acc[r][3] + p.w);
            *reinterpret_cast<float4*>(o + (r0 + r) * WWID + c0) = v;
        }
    }
}

// Output layer, split-K: k[16][64] = (x[16][256] @ W2t(256 x 64) + b2) * efac
// Each group: 1 row x 4 cols over its 128-k slice.
__device__ __forceinline__ void dense_o(const float* __restrict__ x,
                                        const float* __restrict__ Wt,
                                        const float* __restrict__ bias,
                                        float* __restrict__ o,
                                        float* __restrict__ sp,
                                        float efac, int tid) {
    const int kg = tid >> 8;          // 0 or 1
    const int t2 = tid & 255;
    const int row = t2 >> 4;          // 0..15
    const int c0 = (t2 & 15) << 2;    // 0..60
    const int Kh = WWID >> 1;         // 128
    float acc[4];
    if (kg == 0) {
        float4 bv = *reinterpret_cast<const float4*>(bias + c0);
        acc[0] = bv.x; acc[1] = bv.y; acc[2] = bv.z; acc[3] = bv.w;
    } else {
        acc[0] = acc[1] = acc[2] = acc[3] = 0.0f;
    }
    const float* xp = x + row * WWID + kg * Kh;
    const float* wp = Wt + kg * Kh * DD + c0;
    #pragma unroll 2
    for (int k = 0; k < Kh; k += 4) {
        float a[4];
        float w[4][4];
        ld4(a, xp + k);
        ld4(w[0], wp);       ld4(w[1], wp + 64);
        ld4(w[2], wp + 128); ld4(w[3], wp + 192);
        wp += 256;
        #pragma unroll
        for (int kk = 0; kk < 4; ++kk)
            #pragma unroll
            for (int c = 0; c < 4; ++c)
                acc[c] = fmaf(a[kk], w[kk][c], acc[c]);
    }
    if (kg == 1) {
        float4 v; v.x = acc[0]; v.y = acc[1]; v.z = acc[2]; v.w = acc[3];
        *reinterpret_cast<float4*>(sp + row * DD + c0) = v;
    }
    __syncthreads();
    if (kg == 0) {
        float4 p = *reinterpret_cast<const float4*>(sp + row * DD + c0);
        float4 v;
        v.x = (acc[0] + p.x) * efac;
        v.y = (acc[1] + p.y) * efac;
        v.z = (acc[2] + p.z) * efac;
        v.w = (acc[3] + p.w) * efac;
        *reinterpret_cast<float4*>(o + row * DD + c0) = v;
    }
}

// smem layout (floats)
#define OFF_SY   0
#define OFF_SYT  (OFF_SY + MROWS * DD)        // 1024
#define OFF_SH0  (OFF_SYT + MROWS * DD)       // 2048
#define OFF_SH1  (OFF_SH0 + MROWS * WWID)     // 6144
#define OFF_SK   (OFF_SH1 + MROWS * WWID)     // 10240
#define OFF_SP   (OFF_SK + 6 * MROWS * DD)    // 16384 (split-K partials, 16x256)
#define OFF_SB0  (OFF_SP + MROWS * WWID)      // 20480
#define OFF_SB1  (OFF_SB0 + WWID)             // 20736
#define OFF_SB2  (OFF_SB1 + WWID)             // 20992
#define OFF_STS  (OFF_SB2 + DD)               // 21056
#define SMEM_FLOATS (OFF_STS + TT)            // 21088

__global__ void __launch_bounds__(NTHR)
ode_kernel(const float* __restrict__ ts, const float* __restrict__ y0,
           const float* __restrict__ b0, const float* __restrict__ b1,
           const float* __restrict__ b2, float* __restrict__ out) {
    extern __shared__ float sm[];
    float* sy  = sm + OFF_SY;
    float* syt = sm + OFF_SYT;
    float* sh0 = sm + OFF_SH0;
    float* sh1 = sm + OFF_SH1;
    float* sk  = sm + OFF_SK;
    float* sp  = sm + OFF_SP;
    float* sb0 = sm + OFF_SB0;
    float* sb1 = sm + OFF_SB1;
    float* sb2 = sm + OFF_SB2;
    float* sts = sm + OFF_STS;

    const int tid = threadIdx.x;
    const int rb = blockIdx.x * MROWS;

    // Init: load y0 slice, biases, ts; write t=0 output slice.
    {
        float2 v = reinterpret_cast<const float2*>(y0)[rb * (DD / 2) + tid];
        reinterpret_cast<float2*>(sy)[tid] = v;
        reinterpret_cast<float2*>(out)[rb * (DD / 2) + tid] = v;
        if (tid < WWID) { sb0[tid] = b0[tid]; sb1[tid] = b1[tid]; }
        if (tid < DD) sb2[tid] = b2[tid];
        if (tid < TT) sts[tid] = ts[tid];
    }
    __syncthreads();

    float2* sy2  = reinterpret_cast<float2*>(sy);
    float2* syt2 = reinterpret_cast<float2*>(syt);
    float2* k12  = reinterpret_cast<float2*>(sk + 0 * MROWS * DD);
    float2* k22  = reinterpret_cast<float2*>(sk + 1 * MROWS * DD);
    float2* k32  = reinterpret_cast<float2*>(sk + 2 * MROWS * DD);
    float2* k42  = reinterpret_cast<float2*>(sk + 3 * MROWS * DD);
    float2* k52  = reinterpret_cast<float2*>(sk + 4 * MROWS * DD);
    float2* k62  = reinterpret_cast<float2*>(sk + 5 * MROWS * DD);

    for (int iv = 0; iv < TT - 1; ++iv) {
        const float t0 = sts[iv];
        const float dt = sts[iv + 1] - t0;
        const float h = 0.5f * dt;

        for (int sub = 0; sub < 2; ++sub) {
            const float tc = t0 + (float)sub * h;

            // ---- stage 1: k1 = vf(tc, y) ----
            dense_h(sy, DD, g_W0t, sb0, sh0, sp, tid);  __syncthreads();
            dense_h(sh0, WWID, g_W1t, sb1, sh1, sp, tid); __syncthreads();
            dense_o(sh1, g_W2t, sb2, sk + 0 * MROWS * DD, sp, __expf(tc), tid); __syncthreads();

            // ---- stage 2 ----
            syt2[tid] = f2fma(sy2[tid], h * 0.2f, k12[tid]);
            __syncthreads();
            dense_h(syt, DD, g_W0t, sb0, sh0, sp, tid);  __syncthreads();
            dense_h(sh0, WWID, g_W1t, sb1, sh1, sp, tid); __syncthreads();
            dense_o(sh1, g_W2t, sb2, sk + 1 * MROWS * DD, sp, __expf(tc + 0.2f * h), tid); __syncthreads();

            // ---- stage 3 ----
            {
                float2 v = sy2[tid];
                v = f2fma(v, h * (3.0f / 40.0f), k12[tid]);
                v = f2fma(v, h * (9.0f / 40.0f), k22[tid]);
                syt2[tid] = v;
            }
            __syncthreads();
            dense_h(syt, DD, g_W0t, sb0, sh0, sp, tid);  __syncthreads();
            dense_h(sh0, WWID, g_W1t, sb1, sh1, sp, tid); __syncthreads();
            dense_o(sh1, g_W2t, sb2, sk + 2 * MROWS * DD, sp, __expf(tc + 0.3f * h), tid); __syncthreads();

            // ---- stage 4 ----
            {
                float2 v = sy2[tid];
                v = f2fma(v, h * (44.0f / 45.0f),  k12[tid]);
                v = f2fma(v, h * (-56.0f / 15.0f), k22[tid]);
                v = f2fma(v, h * (32.0f / 9.0f),   k32[tid]);
                syt2[tid] = v;
            }
            __syncthreads();
            dense_h(syt, DD, g_W0t, sb0, sh0, sp, tid);  __syncthreads();
            dense_h(sh0, WWID, g_W1t, sb1, sh1, sp, tid); __syncthreads();
            dense_o(sh1, g_W2t, sb2, sk + 3 * MROWS * DD, sp, __expf(tc + 0.8f * h), tid); __syncthreads();

            // ---- stage 5 ----
            {
                float2 v = sy2[tid];
                v = f2fma(v, h * (19372.0f / 6561.0f),  k12[tid]);
                v = f2fma(v, h * (-25360.0f / 2187.0f), k22[tid]);
                v = f2fma(v, h * (64448.0f / 6561.0f),  k32[tid]);
                v = f2fma(v, h * (-212.0f / 729.0f),    k42[tid]);
                syt2[tid] = v;
            }
            __syncthreads();
            dense_h(syt, DD, g_W0t, sb0, sh0, sp, tid);  __syncthreads();
            dense_h(sh0, WWID, g_W1t, sb1, sh1, sp, tid); __syncthreads();
            dense_o(sh1, g_W2t, sb2, sk + 4 * MROWS * DD, sp, __expf(tc + (8.0f / 9.0f) * h), tid); __syncthreads();

            // ---- stage 6 ----
            {
                float2 v = sy2[tid];
                v = f2fma(v, h * (9017.0f / 3168.0f),   k12[tid]);
                v = f2fma(v, h * (-355.0f / 33.0f),     k22[tid]);
                v = f2fma(v, h * (46732.0f / 5247.0f),  k32[tid]);
                v = f2fma(v, h * (49.0f / 176.0f),      k42[tid]);
                v = f2fma(v, h * (-5103.0f / 18656.0f), k52[tid]);
                syt2[tid] = v;
            }
            __syncthreads();
            dense_h(syt, DD, g_W0t, sb0, sh0, sp, tid);  __syncthreads();
            dense_h(sh0, WWID, g_W1t, sb1, sh1, sp, tid); __syncthreads();
            dense_o(sh1, g_W2t, sb2, sk + 5 * MROWS * DD, sp, __expf(tc + h), tid); __syncthreads();

            // ---- final combine ----
            {
                float2 v = sy2[tid];
                v = f2fma(v, h * (35.0f / 384.0f),     k12[tid]);
                v = f2fma(v, h * (500.0f / 1113.0f),   k32[tid]);
                v = f2fma(v, h * (125.0f / 192.0f),    k42[tid]);
                v = f2fma(v, h * (-2187.0f / 6784.0f), k52[tid]);
                v = f2fma(v, h * (11.0f / 84.0f),      k62[tid]);
                sy2[tid] = v;
            }
            __syncthreads();
        }

        // write output slice (iv+1)
        reinterpret_cast<float2*>(out)[((iv + 1) * BB + rb) * (DD / 2) + tid] = sy2[tid];
    }
}

extern "C" void kernel_launch(void* const* d_in, const int* in_sizes, int n_in,
                              void* d_out, int out_size) {
    const float* ts = (const float*)d_in[0];
    const float* y0 = (const float*)d_in[1];
    const float* W0 = (const float*)d_in[2];
    const float* b0 = (const float*)d_in[3];
    const float* W1 = (const float*)d_in[4];
    const float* b1 = (const float*)d_in[5];
    const float* W2 = (const float*)d_in[6];
    const float* b2 = (const float*)d_in[7];
    float* out = (float*)d_out;

    prep_kernel<<<256, 256>>>(W0, W1, W2);

    size_t smem_bytes = SMEM_FLOATS * sizeof(float);
    cudaFuncSetAttribute(ode_kernel, cudaFuncAttributeMaxDynamicSharedMemorySize,
                         (int)smem_bytes);
    ode_kernel<<<NCTA, NTHR, smem_bytes>>>(ts, y0, b0, b1, b2, out);
}

// round 7
// speedup vs baseline: 2.2682x; 1.2483x over previous
#include <cuda_runtime.h>

#define TT 32
#define BB 2048
#define DD 64
#define WWID 256
#define MROWS 16
#define NCTA (BB / MROWS)   // 128
#define NTHR 1024

// Transposed weights, [k][n] layout so weight loads are lane-coalesced.
__device__ __align__(16) float g_W0t[DD * WWID];    // 64 x 256
__device__ __align__(16) float g_W1t[WWID * WWID];  // 256 x 256
__device__ __align__(16) float g_W2t[WWID * DD];    // 256 x 64

__global__ void prep_kernel(const float* __restrict__ W0,
                            const float* __restrict__ W1,
                            const float* __restrict__ W2) {
    int idx = blockIdx.x * blockDim.x + threadIdx.x;
    if (idx < DD * WWID) {              // W0t[k][n] = W0[n][k]
        int k = idx >> 8, n = idx & 255;
        g_W0t[idx] = W0[n * DD + k];
    }
    if (idx < WWID * WWID) {            // W1t[k][n] = W1[n][k]
        int k = idx >> 8, n = idx & 255;
        g_W1t[idx] = W1[n * WWID + k];
    }
    if (idx < WWID * DD) {              // W2t[k][d] = W2[d][k]
        int k = idx >> 6, d = idx & 63;
        g_W2t[idx] = W2[d * WWID + k];
    }
}

__device__ __forceinline__ float tanh_fast(float x) {
    // exact identity tanh(x) = 1 - 2/(e^{2x}+1); ~1e-6 abs err with fast exp/div
    float e = __expf(2.0f * x);
    return 1.0f - __fdividef(2.0f, e + 1.0f);
}

__device__ __forceinline__ void ld4(float* d, const float* p) {
    float4 t = *reinterpret_cast<const float4*>(p);
    d[0] = t.x; d[1] = t.y; d[2] = t.z; d[3] = t.w;
}

// Hidden layer, 4-way split-K over k-groups of 256 threads each.
// out[16][256] = tanh(x[16][K] @ Wt(K x 256) + bias)
// Each group: 4 rows x 4 cols scalar-FFMA tile over its K/4 slice.
// Groups 1..3 write partials to sp; group 0 sums, applies tanh, stores.
__device__ __forceinline__ void dense_h(const float* __restrict__ x, int K,
                                        const float* __restrict__ Wt,
                                        const float* __restrict__ bias,
                                        float* __restrict__ o,
                                        float* __restrict__ sp, int tid) {
    const int kg = tid >> 8;          // 0..3
    const int t2 = tid & 255;
    const int r0 = (t2 >> 6) << 2;    // 0,4,8,12
    const int c0 = (t2 & 63) << 2;    // 0..252
    const int Kq = K >> 2;
    float acc[4][4];
    if (kg == 0) {
        float4 bv = *reinterpret_cast<const float4*>(bias + c0);
        #pragma unroll
        for (int r = 0; r < 4; ++r) {
            acc[r][0] = bv.x; acc[r][1] = bv.y; acc[r][2] = bv.z; acc[r][3] = bv.w;
        }
    } else {
        #pragma unroll
        for (int r = 0; r < 4; ++r)
            #pragma unroll
            for (int c = 0; c < 4; ++c) acc[r][c] = 0.0f;
    }
    const float* xp0 = x + r0 * K + kg * Kq;
    const float* xp1 = xp0 + K;
    const float* xp2 = xp1 + K;
    const float* xp3 = xp2 + K;
    const float* wp = Wt + kg * Kq * WWID + c0;
    #pragma unroll 2
    for (int k = 0; k < Kq; k += 4) {
        float a[4][4];   // [r][kk]
        float w[4][4];   // [kk][c]
        ld4(a[0], xp0 + k); ld4(a[1], xp1 + k);
        ld4(a[2], xp2 + k); ld4(a[3], xp3 + k);
        ld4(w[0], wp);        ld4(w[1], wp + 256);
        ld4(w[2], wp + 512);  ld4(w[3], wp + 768);
        wp += 1024;
        #pragma unroll
        for (int r = 0; r < 4; ++r)
            #pragma unroll
            for (int kk = 0; kk < 4; ++kk)
                #pragma unroll
                for (int c = 0; c < 4; ++c)
                    acc[r][c] = fmaf(a[r][kk], w[kk][c], acc[r][c]);
    }
    if (kg != 0) {
        float* spg = sp + (kg - 1) * MROWS * WWID;
        #pragma unroll
        for (int r = 0; r < 4; ++r) {
            float4 v; v.x = acc[r][0]; v.y = acc[r][1]; v.z = acc[r][2]; v.w = acc[r][3];
            *reinterpret_cast<float4*>(spg + (r0 + r) * WWID + c0) = v;
        }
    }
    __syncthreads();
    if (kg == 0) {
        #pragma unroll
        for (int r = 0; r < 4; ++r) {
            float4 p1 = *reinterpret_cast<const float4*>(sp + 0 * MROWS * WWID + (r0 + r) * WWID + c0);
            float4 p2 = *reinterpret_cast<const float4*>(sp + 1 * MROWS * WWID + (r0 + r) * WWID + c0);
            float4 p3 = *reinterpret_cast<const float4*>(sp + 2 * MROWS * WWID + (r0 + r) * WWID + c0);
            float4 v;
            v.x = tanh_fast(acc[r][0] + p1.x + p2.x + p3.x);
            v.y = tanh_fast(acc[r][1] + p1.y + p2.y + p3.y);
            v.z = tanh_fast(acc[r][2] + p1.z + p2.z + p3.z);
            v.w = tanh_fast(acc[r][3] + p1.w + p2.w + p3.w);
            *reinterpret_cast<float4*>(o + (r0 + r) * WWID + c0) = v;
        }
    }
}

// Output layer, 4-way split-K: k[16][64] = (x[16][256] @ W2t(256 x 64) + b2) * efac
// Each group: 1 row x 4 cols over its 64-k slice.
__device__ __forceinline__ void dense_o(const float* __restrict__ x,
                                        const float* __restrict__ Wt,
                                        const float* __restrict__ bias,
                                        float* __restrict__ o,
                                        float* __restrict__ sp,
                                        float efac, int tid) {
    const int kg = tid >> 8;          // 0..3
    const int t2 = tid & 255;
    const int row = t2 >> 4;          // 0..15
    const int c0 = (t2 & 15) << 2;    // 0..60
    const int Kq = WWID >> 2;         // 64
    float acc[4];
    if (kg == 0) {
        float4 bv = *reinterpret_cast<const float4*>(bias + c0);
        acc[0] = bv.x; acc[1] = bv.y; acc[2] = bv.z; acc[3] = bv.w;
    } else {
        acc[0] = acc[1] = acc[2] = acc[3] = 0.0f;
    }
    const float* xp = x + row * WWID + kg * Kq;
    const float* wp = Wt + kg * Kq * DD + c0;
    #pragma unroll 2
    for (int k = 0; k < Kq; k += 4) {
        float a[4];
        float w[4][4];
        ld4(a, xp + k);
        ld4(w[0], wp);       ld4(w[1], wp + 64);
        ld4(w[2], wp + 128); ld4(w[3], wp + 192);
        wp += 256;
        #pragma unroll
        for (int kk = 0; kk < 4; ++kk)
            #pragma unroll
            for (int c = 0; c < 4; ++c)
                acc[c] = fmaf(a[kk], w[kk][c], acc[c]);
    }
    if (kg != 0) {
        float* spg = sp + (kg - 1) * MROWS * DD;
        float4 v; v.x = acc[0]; v.y = acc[1]; v.z = acc[2]; v.w = acc[3];
        *reinterpret_cast<float4*>(spg + row * DD + c0) = v;
    }
    __syncthreads();
    if (kg == 0) {
        float4 p1 = *reinterpret_cast<const float4*>(sp + 0 * MROWS * DD + row * DD + c0);
        float4 p2 = *reinterpret_cast<const float4*>(sp + 1 * MROWS * DD + row * DD + c0);
        float4 p3 = *reinterpret_cast<const float4*>(sp + 2 * MROWS * DD + row * DD + c0);
        float4 v;
        v.x = (acc[0] + p1.x + p2.x + p3.x) * efac;
        v.y = (acc[1] + p1.y + p2.y + p3.y) * efac;
        v.z = (acc[2] + p1.z + p2.z + p3.z) * efac;
        v.w = (acc[3] + p1.w + p2.w + p3.w) * efac;
        *reinterpret_cast<float4*>(o + row * DD + c0) = v;
    }
}

// smem layout (floats)
#define OFF_SY   0
#define OFF_SYT  (OFF_SY + MROWS * DD)        // 1024
#define OFF_SH0  (OFF_SYT + MROWS * DD)       // 2048
#define OFF_SH1  (OFF_SH0 + MROWS * WWID)     // 6144
#define OFF_SK   (OFF_SH1 + MROWS * WWID)     // 10240
#define OFF_SP   (OFF_SK + 6 * MROWS * DD)    // 16384 (split-K partials, 3 x 16x256)
#define OFF_SB0  (OFF_SP + 3 * MROWS * WWID)  // 28672
#define OFF_SB1  (OFF_SB0 + WWID)             // 28928
#define OFF_SB2  (OFF_SB1 + WWID)             // 29184
#define OFF_STS  (OFF_SB2 + DD)               // 29248
#define SMEM_FLOATS (OFF_STS + TT)            // 29280 (~117 KB)

__global__ void __launch_bounds__(NTHR)
ode_kernel(const float* __restrict__ ts, const float* __restrict__ y0,
           const float* __restrict__ b0, const float* __restrict__ b1,
           const float* __restrict__ b2, float* __restrict__ out) {
    extern __shared__ float sm[];
    float* sy  = sm + OFF_SY;
    float* syt = sm + OFF_SYT;
    float* sh0 = sm + OFF_SH0;
    float* sh1 = sm + OFF_SH1;
    float* sk  = sm + OFF_SK;
    float* sp  = sm + OFF_SP;
    float* sb0 = sm + OFF_SB0;
    float* sb1 = sm + OFF_SB1;
    float* sb2 = sm + OFF_SB2;
    float* sts = sm + OFF_STS;

    const int tid = threadIdx.x;
    const int rb = blockIdx.x * MROWS;

    // Init: load y0 slice (1024 floats, 1 per thread), biases, ts;
    // write t=0 output slice.
    {
        float v = y0[rb * DD + tid];
        sy[tid] = v;
        out[rb * DD + tid] = v;
        if (tid < WWID) { sb0[tid] = b0[tid]; sb1[tid] = b1[tid]; }
        if (tid < DD) sb2[tid] = b2[tid];
        if (tid < TT) sts[tid] = ts[tid];
    }
    __syncthreads();

    float* k1 = sk + 0 * MROWS * DD;
    float* k2 = sk + 1 * MROWS * DD;
    float* k3 = sk + 2 * MROWS * DD;
    float* k4 = sk + 3 * MROWS * DD;
    float* k5 = sk + 4 * MROWS * DD;
    float* k6 = sk + 5 * MROWS * DD;

    for (int iv = 0; iv < TT - 1; ++iv) {
        const float t0 = sts[iv];
        const float dt = sts[iv + 1] - t0;
        const float h = 0.5f * dt;

        for (int sub = 0; sub < 2; ++sub) {
            const float tc = t0 + (float)sub * h;

            // ---- stage 1: k1 = vf(tc, y) ----
            dense_h(sy, DD, g_W0t, sb0, sh0, sp, tid);  __syncthreads();
            dense_h(sh0, WWID, g_W1t, sb1, sh1, sp, tid); __syncthreads();
            dense_o(sh1, g_W2t, sb2, k1, sp, __expf(tc), tid); __syncthreads();

            // ---- stage 2 ----
            syt[tid] = fmaf(h * 0.2f, k1[tid], sy[tid]);
            __syncthreads();
            dense_h(syt, DD, g_W0t, sb0, sh0, sp, tid);  __syncthreads();
            dense_h(sh0, WWID, g_W1t, sb1, sh1, sp, tid); __syncthreads();
            dense_o(sh1, g_W2t, sb2, k2, sp, __expf(tc + 0.2f * h), tid); __syncthreads();

            // ---- stage 3 ----
            {
                float v = sy[tid];
                v = fmaf(h * (3.0f / 40.0f), k1[tid], v);
                v = fmaf(h * (9.0f / 40.0f), k2[tid], v);
                syt[tid] = v;
            }
            __syncthreads();
            dense_h(syt, DD, g_W0t, sb0, sh0, sp, tid);  __syncthreads();
            dense_h(sh0, WWID, g_W1t, sb1, sh1, sp, tid); __syncthreads();
            dense_o(sh1, g_W2t, sb2, k3, sp, __expf(tc + 0.3f * h), tid); __syncthreads();

            // ---- stage 4 ----
            {
                float v = sy[tid];
                v = fmaf(h * (44.0f / 45.0f),  k1[tid], v);
                v = fmaf(h * (-56.0f / 15.0f), k2[tid], v);
                v = fmaf(h * (32.0f / 9.0f),   k3[tid], v);
                syt[tid] = v;
            }
            __syncthreads();
            dense_h(syt, DD, g_W0t, sb0, sh0, sp, tid);  __syncthreads();
            dense_h(sh0, WWID, g_W1t, sb1, sh1, sp, tid); __syncthreads();
            dense_o(sh1, g_W2t, sb2, k4, sp, __expf(tc + 0.8f * h), tid); __syncthreads();

            // ---- stage 5 ----
            {
                float v = sy[tid];
                v = fmaf(h * (19372.0f / 6561.0f),  k1[tid], v);
                v = fmaf(h * (-25360.0f / 2187.0f), k2[tid], v);
                v = fmaf(h * (64448.0f / 6561.0f),  k3[tid], v);
                v = fmaf(h * (-212.0f / 729.0f),    k4[tid], v);
                syt[tid] = v;
            }
            __syncthreads();
            dense_h(syt, DD, g_W0t, sb0, sh0, sp, tid);  __syncthreads();
            dense_h(sh0, WWID, g_W1t, sb1, sh1, sp, tid); __syncthreads();
            dense_o(sh1, g_W2t, sb2, k5, sp, __expf(tc + (8.0f / 9.0f) * h), tid); __syncthreads();

            // ---- stage 6 ----
            {
                float v = sy[tid];
                v = fmaf(h * (9017.0f / 3168.0f),   k1[tid], v);
                v = fmaf(h * (-355.0f / 33.0f),     k2[tid], v);
                v = fmaf(h * (46732.0f / 5247.0f),  k3[tid], v);
                v = fmaf(h * (49.0f / 176.0f),      k4[tid], v);
                v = fmaf(h * (-5103.0f / 18656.0f), k5[tid], v);
                syt[tid] = v;
            }
            __syncthreads();
            dense_h(syt, DD, g_W0t, sb0, sh0, sp, tid);  __syncthreads();
            dense_h(sh0, WWID, g_W1t, sb1, sh1, sp, tid); __syncthreads();
            dense_o(sh1, g_W2t, sb2, k6, sp, __expf(tc + h), tid); __syncthreads();

            // ---- final combine ----
            {
                float v = sy[tid];
                v = fmaf(h * (35.0f / 384.0f),     k1[tid], v);
                v = fmaf(h * (500.0f / 1113.0f),   k3[tid], v);
                v = fmaf(h * (125.0f / 192.0f),    k4[tid], v);
                v = fmaf(h * (-2187.0f / 6784.0f), k5[tid], v);
                v = fmaf(h * (11.0f / 84.0f),      k6[tid], v);
                sy[tid] = v;
            }
            __syncthreads();
        }

        // write output slice (iv+1)
        out[((iv + 1) * BB + rb) * DD + tid] = sy[tid];
    }
}

extern "C" void kernel_launch(void* const* d_in, const int* in_sizes, int n_in,
                              void* d_out, int out_size) {
    const float* ts = (const float*)d_in[0];
    const float* y0 = (const float*)d_in[1];
    const float* W0 = (const float*)d_in[2];
    const float* b0 = (const float*)d_in[3];
    const float* W1 = (const float*)d_in[4];
    const float* b1 = (const float*)d_in[5];
    const float* W2 = (const float*)d_in[6];
    const float* b2 = (const float*)d_in[7];
    float* out = (float*)d_out;

    prep_kernel<<<256, 256>>>(W0, W1, W2);

    size_t smem_bytes = SMEM_FLOATS * sizeof(float);
    cudaFuncSetAttribute(ode_kernel, cudaFuncAttributeMaxDynamicSharedMemorySize,
                         (int)smem_bytes);
    ode_kernel<<<NCTA, NTHR, smem_bytes>>>(ts, y0, b0, b1, b2, out);
}

// round 8
// speedup vs baseline: 2.3126x; 1.0196x over previous
#include <cuda_runtime.h>

#define TT 32
#define BB 2048
#define DD 64
#define WWID 256
#define MROWS 16
#define NCTA (BB / MROWS)   // 128
#define NTHR 1024

// Transposed weights, [k][n] layout so weight loads are lane-coalesced.
__device__ __align__(16) float g_W0t[DD * WWID];    // 64 x 256
__device__ __align__(16) float g_W1t[WWID * WWID];  // 256 x 256
__device__ __align__(16) float g_W2t[WWID * DD];    // 256 x 64

__global__ void prep_kernel(const float* __restrict__ W0,
                            const float* __restrict__ W1,
                            const float* __restrict__ W2) {
    int idx = blockIdx.x * blockDim.x + threadIdx.x;
    if (idx < DD * WWID) {              // W0t[k][n] = W0[n][k]
        int k = idx >> 8, n = idx & 255;
        g_W0t[idx] = W0[n * DD + k];
    }
    if (idx < WWID * WWID) {            // W1t[k][n] = W1[n][k]
        int k = idx >> 8, n = idx & 255;
        g_W1t[idx] = W1[n * WWID + k];
    }
    if (idx < WWID * DD) {              // W2t[k][d] = W2[d][k]
        int k = idx >> 6, d = idx & 63;
        g_W2t[idx] = W2[d * WWID + k];
    }
}

__device__ __forceinline__ float tanh_fast(float x) {
    // exact identity tanh(x) = 1 - 2/(e^{2x}+1); ~1e-6 abs err with fast exp/div
    float e = __expf(2.0f * x);
    return 1.0f - __fdividef(2.0f, e + 1.0f);
}

__device__ __forceinline__ void ld4(float* d, const float* p) {
    float4 t = *reinterpret_cast<const float4*>(p);
    d[0] = t.x; d[1] = t.y; d[2] = t.z; d[3] = t.w;
}

// Hidden layer, 4-way split-K over k-groups of 256 threads each.
// out[16][256] = tanh(x[16][K] @ Wt(K x 256) + bias)
// Each group: 8 rows x 2 cols per thread (2 row-blocks x 128 col-slots)
// over its K/4 slice -> weight redundancy 2x (was 4x).
// Groups 1..3 write partials to sp; group 0 sums, applies tanh, stores.
__device__ __forceinline__ void dense_h(const float* __restrict__ x, int K,
                                        const float* __restrict__ Wt,
                                        const float* __restrict__ bias,
                                        float* __restrict__ o,
                                        float* __restrict__ sp, int tid) {
    const int kg = tid >> 8;            // 0..3
    const int t2 = tid & 255;
    const int r0 = (t2 >> 7) << 3;      // 0 or 8
    const int c0 = (t2 & 127) << 1;     // 0..254
    const int Kq = K >> 2;
    float acc[8][2];
    if (kg == 0) {
        float2 bv = *reinterpret_cast<const float2*>(bias + c0);
        #pragma unroll
        for (int r = 0; r < 8; ++r) { acc[r][0] = bv.x; acc[r][1] = bv.y; }
    } else {
        #pragma unroll
        for (int r = 0; r < 8; ++r) { acc[r][0] = 0.0f; acc[r][1] = 0.0f; }
    }
    const float* xp = x + r0 * K + kg * Kq;
    const float* wp = Wt + kg * Kq * WWID + c0;
    #pragma unroll 2
    for (int k = 0; k < Kq; k += 4) {
        float2 w0 = *reinterpret_cast<const float2*>(wp);
        float2 w1 = *reinterpret_cast<const float2*>(wp + 256);
        float2 w2 = *reinterpret_cast<const float2*>(wp + 512);
        float2 w3 = *reinterpret_cast<const float2*>(wp + 768);
        wp += 1024;
        // rows 0..3 of this thread's 8-row block
        {
            float a[4][4];
            ld4(a[0], xp + 0 * K + k); ld4(a[1], xp + 1 * K + k);
            ld4(a[2], xp + 2 * K + k); ld4(a[3], xp + 3 * K + k);
            #pragma unroll
            for (int r = 0; r < 4; ++r) {
                acc[r][0] = fmaf(a[r][0], w0.x, acc[r][0]);
                acc[r][1] = fmaf(a[r][0], w0.y, acc[r][1]);
                acc[r][0] = fmaf(a[r][1], w1.x, acc[r][0]);
                acc[r][1] = fmaf(a[r][1], w1.y, acc[r][1]);
                acc[r][0] = fmaf(a[r][2], w2.x, acc[r][0]);
                acc[r][1] = fmaf(a[r][2], w2.y, acc[r][1]);
                acc[r][0] = fmaf(a[r][3], w3.x, acc[r][0]);
                acc[r][1] = fmaf(a[r][3], w3.y, acc[r][1]);
            }
        }
        // rows 4..7
        {
            float a[4][4];
            ld4(a[0], xp + 4 * K + k); ld4(a[1], xp + 5 * K + k);
            ld4(a[2], xp + 6 * K + k); ld4(a[3], xp + 7 * K + k);
            #pragma unroll
            for (int r = 0; r < 4; ++r) {
                acc[r + 4][0] = fmaf(a[r][0], w0.x, acc[r + 4][0]);
                acc[r + 4][1] = fmaf(a[r][0], w0.y, acc[r + 4][1]);
                acc[r + 4][0] = fmaf(a[r][1], w1.x, acc[r + 4][0]);
                acc[r + 4][1] = fmaf(a[r][1], w1.y, acc[r + 4][1]);
                acc[r + 4][0] = fmaf(a[r][2], w2.x, acc[r + 4][0]);
                acc[r + 4][1] = fmaf(a[r][2], w2.y, acc[r + 4][1]);
                acc[r + 4][0] = fmaf(a[r][3], w3.x, acc[r + 4][0]);
                acc[r + 4][1] = fmaf(a[r][3], w3.y, acc[r + 4][1]);
            }
        }
    }
    if (kg != 0) {
        float* spg = sp + (kg - 1) * MROWS * WWID;
        #pragma unroll
        for (int r = 0; r < 8; ++r) {
            float2 v; v.x = acc[r][0]; v.y = acc[r][1];
            *reinterpret_cast<float2*>(spg + (r0 + r) * WWID + c0) = v;
        }
    }
    __syncthreads();
    if (kg == 0) {
        #pragma unroll
        for (int r = 0; r < 8; ++r) {
            const int off = (r0 + r) * WWID + c0;
            float2 p1 = *reinterpret_cast<const float2*>(sp + 0 * MROWS * WWID + off);
            float2 p2 = *reinterpret_cast<const float2*>(sp + 1 * MROWS * WWID + off);
            float2 p3 = *reinterpret_cast<const float2*>(sp + 2 * MROWS * WWID + off);
            float2 v;
            v.x = tanh_fast(acc[r][0] + p1.x + p2.x + p3.x);
            v.y = tanh_fast(acc[r][1] + p1.y + p2.y + p3.y);
            *reinterpret_cast<float2*>(o + off) = v;
        }
    }
}

// Output layer, 4-way split-K: k[16][64] = (x[16][256] @ W2t(256 x 64) + b2) * efac
// Each group: 1 row x 4 cols over its 64-k slice. (W2 is small; unchanged.)
__device__ __forceinline__ void dense_o(const float* __restrict__ x,
                                        const float* __restrict__ Wt,
                                        const float* __restrict__ bias,
                                        float* __restrict__ o,
                                        float* __restrict__ sp,
                                        float efac, int tid) {
    const int kg = tid >> 8;          // 0..3
    const int t2 = tid & 255;
    const int row = t2 >> 4;          // 0..15
    const int c0 = (t2 & 15) << 2;    // 0..60
    const int Kq = WWID >> 2;         // 64
    float acc[4];
    if (kg == 0) {
        float4 bv = *reinterpret_cast<const float4*>(bias + c0);
        acc[0] = bv.x; acc[1] = bv.y; acc[2] = bv.z; acc[3] = bv.w;
    } else {
        acc[0] = acc[1] = acc[2] = acc[3] = 0.0f;
    }
    const float* xp = x + row * WWID + kg * Kq;
    const float* wp = Wt + kg * Kq * DD + c0;
    #pragma unroll 2
    for (int k = 0; k < Kq; k += 4) {
        float a[4];
        float w[4][4];
        ld4(a, xp + k);
        ld4(w[0], wp);       ld4(w[1], wp + 64);
        ld4(w[2], wp + 128); ld4(w[3], wp + 192);
        wp += 256;
        #pragma unroll
        for (int kk = 0; kk < 4; ++kk)
            #pragma unroll
            for (int c = 0; c < 4; ++c)
                acc[c] = fmaf(a[kk], w[kk][c], acc[c]);
    }
    if (kg != 0) {
        float* spg = sp + (kg - 1) * MROWS * DD;
        float4 v; v.x = acc[0]; v.y = acc[1]; v.z = acc[2]; v.w = acc[3];
        *reinterpret_cast<float4*>(spg + row * DD + c0) = v;
    }
    __syncthreads();
    if (kg == 0) {
        float4 p1 = *reinterpret_cast<const float4*>(sp + 0 * MROWS * DD + row * DD + c0);
        float4 p2 = *reinterpret_cast<const float4*>(sp + 1 * MROWS * DD + row * DD + c0);
        float4 p3 = *reinterpret_cast<const float4*>(sp + 2 * MROWS * DD + row * DD + c0);
        float4 v;
        v.x = (acc[0] + p1.x + p2.x + p3.x) * efac;
        v.y = (acc[1] + p1.y + p2.y + p3.y) * efac;
        v.z = (acc[2] + p1.z + p2.z + p3.z) * efac;
        v.w = (acc[3] + p1.w + p2.w + p3.w) * efac;
        *reinterpret_cast<float4*>(o + row * DD + c0) = v;
    }
}

// smem layout (floats)
#define OFF_SY   0
#define OFF_SYT  (OFF_SY + MROWS * DD)        // 1024
#define OFF_SH0  (OFF_SYT + MROWS * DD)       // 2048
#define OFF_SH1  (OFF_SH0 + MROWS * WWID)     // 6144
#define OFF_SK   (OFF_SH1 + MROWS * WWID)     // 10240
#define OFF_SP   (OFF_SK + 6 * MROWS * DD)    // 16384 (split-K partials, 3 x 16x256)
#define OFF_SB0  (OFF_SP + 3 * MROWS * WWID)  // 28672
#define OFF_SB1  (OFF_SB0 + WWID)             // 28928
#define OFF_SB2  (OFF_SB1 + WWID)             // 29184
#define OFF_STS  (OFF_SB2 + DD)               // 29248
#define SMEM_FLOATS (OFF_STS + TT)            // 29280 (~117 KB)

__global__ void __launch_bounds__(NTHR)
ode_kernel(const float* __restrict__ ts, const float* __restrict__ y0,
           const float* __restrict__ b0, const float* __restrict__ b1,
           const float* __restrict__ b2, float* __restrict__ out) {
    extern __shared__ float sm[];
    float* sy  = sm + OFF_SY;
    float* syt = sm + OFF_SYT;
    float* sh0 = sm + OFF_SH0;
    float* sh1 = sm + OFF_SH1;
    float* sk  = sm + OFF_SK;
    float* sp  = sm + OFF_SP;
    float* sb0 = sm + OFF_SB0;
    float* sb1 = sm + OFF_SB1;
    float* sb2 = sm + OFF_SB2;
    float* sts = sm + OFF_STS;

    const int tid = threadIdx.x;
    const int rb = blockIdx.x * MROWS;

    // Init: load y0 slice (1024 floats, 1 per thread), biases, ts;
    // write t=0 output slice.
    {
        float v = y0[rb * DD + tid];
        sy[tid] = v;
        out[rb * DD + tid] = v;
        if (tid < WWID) { sb0[tid] = b0[tid]; sb1[tid] = b1[tid]; }
        if (tid < DD) sb2[tid] = b2[tid];
        if (tid < TT) sts[tid] = ts[tid];
    }
    __syncthreads();

    float* k1 = sk + 0 * MROWS * DD;
    float* k2 = sk + 1 * MROWS * DD;
    float* k3 = sk + 2 * MROWS * DD;
    float* k4 = sk + 3 * MROWS * DD;
    float* k5 = sk + 4 * MROWS * DD;
    float* k6 = sk + 5 * MROWS * DD;

    for (int iv = 0; iv < TT - 1; ++iv) {
        const float t0 = sts[iv];
        const float dt = sts[iv + 1] - t0;
        const float h = 0.5f * dt;

        for (int sub = 0; sub < 2; ++sub) {
            const float tc = t0 + (float)sub * h;

            // ---- stage 1: k1 = vf(tc, y) ----
            dense_h(sy, DD, g_W0t, sb0, sh0, sp, tid);  __syncthreads();
            dense_h(sh0, WWID, g_W1t, sb1, sh1, sp, tid); __syncthreads();
            dense_o(sh1, g_W2t, sb2, k1, sp, __expf(tc), tid); __syncthreads();

            // ---- stage 2 ----
            syt[tid] = fmaf(h * 0.2f, k1[tid], sy[tid]);
            __syncthreads();
            dense_h(syt, DD, g_W0t, sb0, sh0, sp, tid);  __syncthreads();
            dense_h(sh0, WWID, g_W1t, sb1, sh1, sp, tid); __syncthreads();
            dense_o(sh1, g_W2t, sb2, k2, sp, __expf(tc + 0.2f * h), tid); __syncthreads();

            // ---- stage 3 ----
            {
                float v = sy[tid];
                v = fmaf(h * (3.0f / 40.0f), k1[tid], v);
                v = fmaf(h * (9.0f / 40.0f), k2[tid], v);
                syt[tid] = v;
            }
            __syncthreads();
            dense_h(syt, DD, g_W0t, sb0, sh0, sp, tid);  __syncthreads();
            dense_h(sh0, WWID, g_W1t, sb1, sh1, sp, tid); __syncthreads();
            dense_o(sh1, g_W2t, sb2, k3, sp, __expf(tc + 0.3f * h), tid); __syncthreads();

            // ---- stage 4 ----
            {
                float v = sy[tid];
                v = fmaf(h * (44.0f / 45.0f),  k1[tid], v);
                v = fmaf(h * (-56.0f / 15.0f), k2[tid], v);
                v = fmaf(h * (32.0f / 9.0f),   k3[tid], v);
                syt[tid] = v;
            }
            __syncthreads();
            dense_h(syt, DD, g_W0t, sb0, sh0, sp, tid);  __syncthreads();
            dense_h(sh0, WWID, g_W1t, sb1, sh1, sp, tid); __syncthreads();
            dense_o(sh1, g_W2t, sb2, k4, sp, __expf(tc + 0.8f * h), tid); __syncthreads();

            // ---- stage 5 ----
            {
                float v = sy[tid];
                v = fmaf(h * (19372.0f / 6561.0f),  k1[tid], v);
                v = fmaf(h * (-25360.0f / 2187.0f), k2[tid], v);
                v = fmaf(h * (64448.0f / 6561.0f),  k3[tid], v);
                v = fmaf(h * (-212.0f / 729.0f),    k4[tid], v);
                syt[tid] = v;
            }
            __syncthreads();
            dense_h(syt, DD, g_W0t, sb0, sh0, sp, tid);  __syncthreads();
            dense_h(sh0, WWID, g_W1t, sb1, sh1, sp, tid); __syncthreads();
            dense_o(sh1, g_W2t, sb2, k5, sp, __expf(tc + (8.0f / 9.0f) * h), tid); __syncthreads();

            // ---- stage 6 ----
            {
                float v = sy[tid];
                v = fmaf(h * (9017.0f / 3168.0f),   k1[tid], v);
                v = fmaf(h * (-355.0f / 33.0f),     k2[tid], v);
                v = fmaf(h * (46732.0f / 5247.0f),  k3[tid], v);
                v = fmaf(h * (49.0f / 176.0f),      k4[tid], v);
                v = fmaf(h * (-5103.0f / 18656.0f), k5[tid], v);
                syt[tid] = v;
            }
            __syncthreads();
            dense_h(syt, DD, g_W0t, sb0, sh0, sp, tid);  __syncthreads();
            dense_h(sh0, WWID, g_W1t, sb1, sh1, sp, tid); __syncthreads();
            dense_o(sh1, g_W2t, sb2, k6, sp, __expf(tc + h), tid); __syncthreads();

            // ---- final combine ----
            {
                float v = sy[tid];
                v = fmaf(h * (35.0f / 384.0f),     k1[tid], v);
                v = fmaf(h * (500.0f / 1113.0f),   k3[tid], v);
                v = fmaf(h * (125.0f / 192.0f),    k4[tid], v);
                v = fmaf(h * (-2187.0f / 6784.0f), k5[tid], v);
                v = fmaf(h * (11.0f / 84.0f),      k6[tid], v);
                sy[tid] = v;
            }
            __syncthreads();
        }

        // write output slice (iv+1)
        out[((iv + 1) * BB + rb) * DD + tid] = sy[tid];
    }
}

extern "C" void kernel_launch(void* const* d_in, const int* in_sizes, int n_in,
                              void* d_out, int out_size) {
    const float* ts = (const float*)d_in[0];
    const float* y0 = (const float*)d_in[1];
    const float* W0 = (const float*)d_in[2];
    const float* b0 = (const float*)d_in[3];
    const float* W1 = (const float*)d_in[4];
    const float* b1 = (const float*)d_in[5];
    const float* W2 = (const float*)d_in[6];
    const float* b2 = (const float*)d_in[7];
    float* out = (float*)d_out;

    prep_kernel<<<256, 256>>>(W0, W1, W2);

    size_t smem_bytes = SMEM_FLOATS * sizeof(float);
    cudaFuncSetAttribute(ode_kernel, cudaFuncAttributeMaxDynamicSharedMemorySize,
                         (int)smem_bytes);
    ode_kernel<<<NCTA, NTHR, smem_bytes>>>(ts, y0, b0, b1, b2, out);
}

// round 9
// speedup vs baseline: 2.4429x; 1.0563x over previous
#include <cuda_runtime.h>

#define TT 32
#define BB 2048
#define DD 64
#define WWID 256
#define MROWS 14
#define NCTA ((BB + MROWS - 1) / MROWS)   // 147
#define NTHR 1024
#define NROWSD (MROWS * DD)               // 896

// Transposed weights, [k][n] layout so weight loads are lane-coalesced.
__device__ __align__(16) float g_W0t[DD * WWID];    // 64 x 256
__device__ __align__(16) float g_W1t[WWID * WWID];  // 256 x 256
__device__ __align__(16) float g_W2t[WWID * DD];    // 256 x 64

__global__ void prep_kernel(const float* __restrict__ W0,
                            const float* __restrict__ W1,
                            const float* __restrict__ W2) {
    int idx = blockIdx.x * blockDim.x + threadIdx.x;
    if (idx < DD * WWID) {              // W0t[k][n] = W0[n][k]
        int k = idx >> 8, n = idx & 255;
        g_W0t[idx] = W0[n * DD + k];
    }
    if (idx < WWID * WWID) {            // W1t[k][n] = W1[n][k]
        int k = idx >> 8, n = idx & 255;
        g_W1t[idx] = W1[n * WWID + k];
    }
    if (idx < WWID * DD) {              // W2t[k][d] = W2[d][k]
        int k = idx >> 6, d = idx & 63;
        g_W2t[idx] = W2[d * WWID + k];
    }
}

__device__ __forceinline__ float tanh_fast(float x) {
    // exact identity tanh(x) = 1 - 2/(e^{2x}+1); ~1e-6 abs err with fast exp/div
    float e = __expf(2.0f * x);
    return 1.0f - __fdividef(2.0f, e + 1.0f);
}

__device__ __forceinline__ void ld4(float* d, const float* p) {
    float4 t = *reinterpret_cast<const float4*>(p);
    d[0] = t.x; d[1] = t.y; d[2] = t.z; d[3] = t.w;
}

// Hidden layer, 4-way split-K over k-groups of 256 threads each.
// out[14][256] = tanh(x[14][K] @ Wt(K x 256) + bias)
// Each group: 7 rows x 2 cols per thread (2 row-blocks x 128 col-slots)
// over its K/4 slice. Groups 1..3 write partials to sp; group 0 sums+tanh.
__device__ __forceinline__ void dense_h(const float* __restrict__ x, int K,
                                        const float* __restrict__ Wt,
                                        const float* __restrict__ bias,
                                        float* __restrict__ o,
                                        float* __restrict__ sp, int tid) {
    const int kg = tid >> 8;            // 0..3
    const int t2 = tid & 255;
    const int r0 = (t2 >> 7) * 7;       // 0 or 7
    const int c0 = (t2 & 127) << 1;     // 0..254
    const int Kq = K >> 2;
    float acc[7][2];
    if (kg == 0) {
        float2 bv = *reinterpret_cast<const float2*>(bias + c0);
        #pragma unroll
        for (int r = 0; r < 7; ++r) { acc[r][0] = bv.x; acc[r][1] = bv.y; }
    } else {
        #pragma unroll
        for (int r = 0; r < 7; ++r) { acc[r][0] = 0.0f; acc[r][1] = 0.0f; }
    }
    const float* xp = x + r0 * K + kg * Kq;
    const float* wp = Wt + kg * Kq * WWID + c0;
    #pragma unroll 2
    for (int k = 0; k < Kq; k += 4) {
        float2 w0 = *reinterpret_cast<const float2*>(wp);
        float2 w1 = *reinterpret_cast<const float2*>(wp + 256);
        float2 w2 = *reinterpret_cast<const float2*>(wp + 512);
        float2 w3 = *reinterpret_cast<const float2*>(wp + 768);
        wp += 1024;
        // rows 0..3 of this thread's 7-row block
        {
            float a[4][4];
            ld4(a[0], xp + 0 * K + k); ld4(a[1], xp + 1 * K + k);
            ld4(a[2], xp + 2 * K + k); ld4(a[3], xp + 3 * K + k);
            #pragma unroll
            for (int r = 0; r < 4; ++r) {
                acc[r][0] = fmaf(a[r][0], w0.x, acc[r][0]);
                acc[r][1] = fmaf(a[r][0], w0.y, acc[r][1]);
                acc[r][0] = fmaf(a[r][1], w1.x, acc[r][0]);
                acc[r][1] = fmaf(a[r][1], w1.y, acc[r][1]);
                acc[r][0] = fmaf(a[r][2], w2.x, acc[r][0]);
                acc[r][1] = fmaf(a[r][2], w2.y, acc[r][1]);
                acc[r][0] = fmaf(a[r][3], w3.x, acc[r][0]);
                acc[r][1] = fmaf(a[r][3], w3.y, acc[r][1]);
            }
        }
        // rows 4..6
        {
            float a[3][4];
            ld4(a[0], xp + 4 * K + k); ld4(a[1], xp + 5 * K + k);
            ld4(a[2], xp + 6 * K + k);
            #pragma unroll
            for (int r = 0; r < 3; ++r) {
                acc[r + 4][0] = fmaf(a[r][0], w0.x, acc[r + 4][0]);
                acc[r + 4][1] = fmaf(a[r][0], w0.y, acc[r + 4][1]);
                acc[r + 4][0] = fmaf(a[r][1], w1.x, acc[r + 4][0]);
                acc[r + 4][1] = fmaf(a[r][1], w1.y, acc[r + 4][1]);
                acc[r + 4][0] = fmaf(a[r][2], w2.x, acc[r + 4][0]);
                acc[r + 4][1] = fmaf(a[r][2], w2.y, acc[r + 4][1]);
                acc[r + 4][0] = fmaf(a[r][3], w3.x, acc[r + 4][0]);
                acc[r + 4][1] = fmaf(a[r][3], w3.y, acc[r + 4][1]);
            }
        }
    }
    if (kg != 0) {
        float* spg = sp + (kg - 1) * MROWS * WWID;
        #pragma unroll
        for (int r = 0; r < 7; ++r) {
            float2 v; v.x = acc[r][0]; v.y = acc[r][1];
            *reinterpret_cast<float2*>(spg + (r0 + r) * WWID + c0) = v;
        }
    }
    __syncthreads();
    if (kg == 0) {
        #pragma unroll
        for (int r = 0; r < 7; ++r) {
            const int off = (r0 + r) * WWID + c0;
            float2 p1 = *reinterpret_cast<const float2*>(sp + 0 * MROWS * WWID + off);
            float2 p2 = *reinterpret_cast<const float2*>(sp + 1 * MROWS * WWID + off);
            float2 p3 = *reinterpret_cast<const float2*>(sp + 2 * MROWS * WWID + off);
            float2 v;
            v.x = tanh_fast(acc[r][0] + p1.x + p2.x + p3.x);
            v.y = tanh_fast(acc[r][1] + p1.y + p2.y + p3.y);
            *reinterpret_cast<float2*>(o + off) = v;
        }
    }
}

// Output layer, 4-way split-K: k[14][64] = (x[14][256] @ W2t(256 x 64) + b2) * efac
// Each group: 1 row x 4 cols over its 64-k slice; 16-row indexing, rows >= 14 masked.
__device__ __forceinline__ void dense_o(const float* __restrict__ x,
                                        const float* __restrict__ Wt,
                                        const float* __restrict__ bias,
                                        float* __restrict__ o,
                                        float* __restrict__ sp,
                                        float efac, int tid) {
    const int kg = tid >> 8;          // 0..3
    const int t2 = tid & 255;
    const int row = t2 >> 4;          // 0..15 (rows 14,15 masked)
    const int c0 = (t2 & 15) << 2;    // 0..60
    const int Kq = WWID >> 2;         // 64
    const bool act = (row < MROWS);
    float acc[4];
    if (kg == 0) {
        float4 bv = *reinterpret_cast<const float4*>(bias + c0);
        acc[0] = bv.x; acc[1] = bv.y; acc[2] = bv.z; acc[3] = bv.w;
    } else {
        acc[0] = acc[1] = acc[2] = acc[3] = 0.0f;
    }
    // clamp row for reads so we never index past sh1's region
    const int rrow = act ? row : 0;
    const float* xp = x + rrow * WWID + kg * Kq;
    const float* wp = Wt + kg * Kq * DD + c0;
    #pragma unroll 2
    for (int k = 0; k < Kq; k += 4) {
        float a[4];
        float w[4][4];
        ld4(a, xp + k);
        ld4(w[0], wp);       ld4(w[1], wp + 64);
        ld4(w[2], wp + 128); ld4(w[3], wp + 192);
        wp += 256;
        #pragma unroll
        for (int kk = 0; kk < 4; ++kk)
            #pragma unroll
            for (int c = 0; c < 4; ++c)
                acc[c] = fmaf(a[kk], w[kk][c], acc[c]);
    }
    if (kg != 0 && act) {
        float* spg = sp + (kg - 1) * MROWS * DD;
        float4 v; v.x = acc[0]; v.y = acc[1]; v.z = acc[2]; v.w = acc[3];
        *reinterpret_cast<float4*>(spg + row * DD + c0) = v;
    }
    __syncthreads();
    if (kg == 0 && act) {
        float4 p1 = *reinterpret_cast<const float4*>(sp + 0 * MROWS * DD + row * DD + c0);
        float4 p2 = *reinterpret_cast<const float4*>(sp + 1 * MROWS * DD + row * DD + c0);
        float4 p3 = *reinterpret_cast<const float4*>(sp + 2 * MROWS * DD + row * DD + c0);
        float4 v;
        v.x = (acc[0] + p1.x + p2.x + p3.x) * efac;
        v.y = (acc[1] + p1.y + p2.y + p3.y) * efac;
        v.z = (acc[2] + p1.z + p2.z + p3.z) * efac;
        v.w = (acc[3] + p1.w + p2.w + p3.w) * efac;
        *reinterpret_cast<float4*>(o + row * DD + c0) = v;
    }
}

// smem layout (floats)
#define OFF_SY   0
#define OFF_SYT  (OFF_SY + NROWSD)            // 896
#define OFF_SH0  (OFF_SYT + NROWSD)           // 1792
#define OFF_SH1  (OFF_SH0 + MROWS * WWID)     // 5376
#define OFF_SK   (OFF_SH1 + MROWS * WWID)     // 8960
#define OFF_SP   (OFF_SK + 6 * NROWSD)        // 14336 (split-K partials, 3 x 14x256)
#define OFF_SB0  (OFF_SP + 3 * MROWS * WWID)  // 25088
#define OFF_SB1  (OFF_SB0 + WWID)             // 25344
#define OFF_SB2  (OFF_SB1 + WWID)             // 25600
#define OFF_STS  (OFF_SB2 + DD)               // 25664
#define SMEM_FLOATS (OFF_STS + TT)            // 25696 (~103 KB)

__global__ void __launch_bounds__(NTHR)
ode_kernel(const float* __restrict__ ts, const float* __restrict__ y0,
           const float* __restrict__ b0, const float* __restrict__ b1,
           const float* __restrict__ b2, float* __restrict__ out) {
    extern __shared__ float sm[];
    float* sy  = sm + OFF_SY;
    float* syt = sm + OFF_SYT;
    float* sh0 = sm + OFF_SH0;
    float* sh1 = sm + OFF_SH1;
    float* sk  = sm + OFF_SK;
    float* sp  = sm + OFF_SP;
    float* sb0 = sm + OFF_SB0;
    float* sb1 = sm + OFF_SB1;
    float* sb2 = sm + OFF_SB2;
    float* sts = sm + OFF_STS;

    const int tid = threadIdx.x;
    const int rb = blockIdx.x * MROWS;
    // valid element count for this CTA's [rows x DD] slab in global memory
    const bool valid = (tid < NROWSD) && (rb * DD + tid < BB * DD);

    // Init: load y0 slice (clamped), biases, ts; write t=0 output slice (masked).
    {
        if (tid < NROWSD) {
            int gi = rb * DD + tid;
            float v = y0[valid ? gi : 0];
            sy[tid] = v;
            if (valid) out[gi] = v;
        }
        if (tid < WWID) { sb0[tid] = b0[tid]; sb1[tid] = b1[tid]; }
        if (tid < DD) sb2[tid] = b2[tid];
        if (tid < TT) sts[tid] = ts[tid];
    }
    __syncthreads();

    float* k1 = sk + 0 * NROWSD;
    float* k2 = sk + 1 * NROWSD;
    float* k3 = sk + 2 * NROWSD;
    float* k4 = sk + 3 * NROWSD;
    float* k5 = sk + 4 * NROWSD;
    float* k6 = sk + 5 * NROWSD;

    for (int iv = 0; iv < TT - 1; ++iv) {
        const float t0 = sts[iv];
        const float dt = sts[iv + 1] - t0;
        const float h = 0.5f * dt;

        for (int sub = 0; sub < 2; ++sub) {
            const float tc = t0 + (float)sub * h;

            // ---- stage 1: k1 = vf(tc, y) ----
            dense_h(sy, DD, g_W0t, sb0, sh0, sp, tid);  __syncthreads();
            dense_h(sh0, WWID, g_W1t, sb1, sh1, sp, tid); __syncthreads();
            dense_o(sh1, g_W2t, sb2, k1, sp, __expf(tc), tid); __syncthreads();

            // ---- stage 2 ----
            if (tid < NROWSD) syt[tid] = fmaf(h * 0.2f, k1[tid], sy[tid]);
            __syncthreads();
            dense_h(syt, DD, g_W0t, sb0, sh0, sp, tid);  __syncthreads();
            dense_h(sh0, WWID, g_W1t, sb1, sh1, sp, tid); __syncthreads();
            dense_o(sh1, g_W2t, sb2, k2, sp, __expf(tc + 0.2f * h), tid); __syncthreads();

            // ---- stage 3 ----
            if (tid < NROWSD) {
                float v = sy[tid];
                v = fmaf(h * (3.0f / 40.0f), k1[tid], v);
                v = fmaf(h * (9.0f / 40.0f), k2[tid], v);
                syt[tid] = v;
            }
            __syncthreads();
            dense_h(syt, DD, g_W0t, sb0, sh0, sp, tid);  __syncthreads();
            dense_h(sh0, WWID, g_W1t, sb1, sh1, sp, tid); __syncthreads();
            dense_o(sh1, g_W2t, sb2, k3, sp, __expf(tc + 0.3f * h), tid); __syncthreads();

            // ---- stage 4 ----
            if (tid < NROWSD) {
                float v = sy[tid];
                v = fmaf(h * (44.0f / 45.0f),  k1[tid], v);
                v = fmaf(h * (-56.0f / 15.0f), k2[tid], v);
                v = fmaf(h * (32.0f / 9.0f),   k3[tid], v);
                syt[tid] = v;
            }
            __syncthreads();
            dense_h(syt, DD, g_W0t, sb0, sh0, sp, tid);  __syncthreads();
            dense_h(sh0, WWID, g_W1t, sb1, sh1, sp, tid); __syncthreads();
            dense_o(sh1, g_W2t, sb2, k4, sp, __expf(tc + 0.8f * h), tid); __syncthreads();

            // ---- stage 5 ----
            if (tid < NROWSD) {
                float v = sy[tid];
                v = fmaf(h * (19372.0f / 6561.0f),  k1[tid], v);
                v = fmaf(h * (-25360.0f / 2187.0f), k2[tid], v);
                v = fmaf(h * (64448.0f / 6561.0f),  k3[tid], v);
                v = fmaf(h * (-212.0f / 729.0f),    k4[tid], v);
                syt[tid] = v;
            }
            __syncthreads();
            dense_h(syt, DD, g_W0t, sb0, sh0, sp, tid);  __syncthreads();
            dense_h(sh0, WWID, g_W1t, sb1, sh1, sp, tid); __syncthreads();
            dense_o(sh1, g_W2t, sb2, k5, sp, __expf(tc + (8.0f / 9.0f) * h), tid); __syncthreads();

            // ---- stage 6 ----
            if (tid < NROWSD) {
                float v = sy[tid];
                v = fmaf(h * (9017.0f / 3168.0f),   k1[tid], v);
                v = fmaf(h * (-355.0f / 33.0f),     k2[tid], v);
                v = fmaf(h * (46732.0f / 5247.0f),  k3[tid], v);
                v = fmaf(h * (49.0f / 176.0f),      k4[tid], v);
                v = fmaf(h * (-5103.0f / 18656.0f), k5[tid], v);
                syt[tid] = v;
            }
            __syncthreads();
            dense_h(syt, DD, g_W0t, sb0, sh0, sp, tid);  __syncthreads();
            dense_h(sh0, WWID, g_W1t, sb1, sh1, sp, tid); __syncthreads();
            dense_o(sh1, g_W2t, sb2, k6, sp, __expf(tc + h), tid); __syncthreads();

            // ---- final combine ----
            if (tid < NROWSD) {
                float v = sy[tid];
                v = fmaf(h * (35.0f / 384.0f),     k1[tid], v);
                v = fmaf(h * (500.0f / 1113.0f),   k3[tid], v);
                v = fmaf(h * (125.0f / 192.0f),    k4[tid], v);
                v = fmaf(h * (-2187.0f / 6784.0f), k5[tid], v);
                v = fmaf(h * (11.0f / 84.0f),      k6[tid], v);
                sy[tid] = v;
            }
            __syncthreads();
        }

        // write output slice (iv+1), masked
        if (valid) out[(iv + 1) * (BB * DD) + rb * DD + tid] = sy[tid];
    }
}

extern "C" void kernel_launch(void* const* d_in, const int* in_sizes, int n_in,
                              void* d_out, int out_size) {
    const float* ts = (const float*)d_in[0];
    const float* y0 = (const float*)d_in[1];
    const float* W0 = (const float*)d_in[2];
    const float* b0 = (const float*)d_in[3];
    const float* W1 = (const float*)d_in[4];
    const float* b1 = (const float*)d_in[5];
    const float* W2 = (const float*)d_in[6];
    const float* b2 = (const float*)d_in[7];
    float* out = (float*)d_out;

    prep_kernel<<<256, 256>>>(W0, W1, W2);

    size_t smem_bytes = SMEM_FLOATS * sizeof(float);
    cudaFuncSetAttribute(ode_kernel, cudaFuncAttributeMaxDynamicSharedMemorySize,
                         (int)smem_bytes);
    ode_kernel<<<NCTA, NTHR, smem_bytes>>>(ts, y0, b0, b1, b2, out);
}